// round 6
// baseline (speedup 1.0000x reference)
#include <cuda_runtime.h>
#include <cuda_fp16.h>
#include <math.h>
#include <stdint.h>

#define TOK  8192
#define DDIM 512
#define HDIM 2048
#define NEXP 4

// ---------------- device scratch ----------------
__device__ int   g_cnt[NEXP];
__device__ int   g_bucket[NEXP * TOK];
__device__ float g_sw[TOK];

__device__ __half g_xf[(size_t)TOK * DDIM];
__device__ __half g_he[(size_t)TOK * HDIM];           // expert-path hidden
__device__ __half g_hs[(size_t)TOK * HDIM];           // shared-path hidden
__device__ __half g_w1[(size_t)NEXP * DDIM * HDIM];   // [E][D][H]
__device__ __half g_w2[(size_t)NEXP * HDIM * DDIM];   // [E][H][D]
__device__ __half g_s1[(size_t)DDIM * HDIM];          // [D][H]
__device__ __half g_s2[(size_t)HDIM * DDIM];          // [H][D]

// ---------------- helpers ----------------
__device__ __forceinline__ uint32_t smem_u32(const void* p) {
    uint32_t a;
    asm("{ .reg .u64 t; cvta.to.shared.u64 t, %1; cvt.u32.u64 %0, t; }" : "=r"(a) : "l"(p));
    return a;
}
__device__ __forceinline__ void cp16(uint32_t dst, const void* src, bool valid) {
    int sz = valid ? 16 : 0;
    asm volatile("cp.async.cg.shared.global [%0], [%1], 16, %2;\n" :: "r"(dst), "l"(src), "r"(sz));
}
#define CP_COMMIT() asm volatile("cp.async.commit_group;\n" ::: "memory")
#define CP_WAIT2()  asm volatile("cp.async.wait_group 2;\n" ::: "memory")

__device__ __forceinline__ void ldsm4(uint32_t& r0, uint32_t& r1, uint32_t& r2, uint32_t& r3,
                                      uint32_t a) {
    asm volatile("ldmatrix.sync.aligned.m8n8.x4.shared.b16 {%0,%1,%2,%3}, [%4];"
        : "=r"(r0), "=r"(r1), "=r"(r2), "=r"(r3) : "r"(a));
}
__device__ __forceinline__ void ldsm4t(uint32_t& r0, uint32_t& r1, uint32_t& r2, uint32_t& r3,
                                       uint32_t a) {
    asm volatile("ldmatrix.sync.aligned.m8n8.x4.trans.shared.b16 {%0,%1,%2,%3}, [%4];"
        : "=r"(r0), "=r"(r1), "=r"(r2), "=r"(r3) : "r"(a));
}
__device__ __forceinline__ void mma16816(float* c, const uint32_t* a, const uint32_t* b) {
    asm volatile("mma.sync.aligned.m16n8k16.row.col.f32.f16.f16.f32 "
        "{%0,%1,%2,%3}, {%4,%5,%6,%7}, {%8,%9}, {%0,%1,%2,%3};"
        : "+f"(c[0]), "+f"(c[1]), "+f"(c[2]), "+f"(c[3])
        : "r"(a[0]), "r"(a[1]), "r"(a[2]), "r"(a[3]), "r"(b[0]), "r"(b[1]));
}

// ---------------- zero counters ----------------
__global__ void zero_kernel() {
    if (threadIdx.x < NEXP) g_cnt[threadIdx.x] = 0;
}

// ---------------- router ----------------
__global__ void router_kernel(const float* __restrict__ x,
                              const float* __restrict__ gW,
                              const float* __restrict__ gb,
                              const float* __restrict__ shw,
                              float* __restrict__ gate_out) {
    int t = (blockIdx.x * blockDim.x + threadIdx.x) >> 5;
    int lane = threadIdx.x & 31;
    if (t >= TOK) return;
    const float* xr = x + (size_t)t * DDIM;
    float a0 = 0.f, a1 = 0.f, a2 = 0.f, a3 = 0.f;
    for (int j = lane; j < DDIM; j += 32) {
        float v = xr[j];
        float4 w = *(const float4*)(gW + 4 * j);
        a0 = fmaf(v, w.x, a0); a1 = fmaf(v, w.y, a1);
        a2 = fmaf(v, w.z, a2); a3 = fmaf(v, w.w, a3);
    }
    #pragma unroll
    for (int off = 16; off > 0; off >>= 1) {
        a0 += __shfl_xor_sync(0xffffffffu, a0, off);
        a1 += __shfl_xor_sync(0xffffffffu, a1, off);
        a2 += __shfl_xor_sync(0xffffffffu, a2, off);
        a3 += __shfl_xor_sync(0xffffffffu, a3, off);
    }
    if (lane == 0) {
        float l[4] = {a0 + gb[0], a1 + gb[1], a2 + gb[2], a3 + gb[3]};
        float m = fmaxf(fmaxf(l[0], l[1]), fmaxf(l[2], l[3]));
        float ex[4], s = 0.f;
        #pragma unroll
        for (int e = 0; e < 4; e++) { ex[e] = expf(l[e] - m); s += ex[e]; }
        float inv = 1.f / s;
        float best = -1.f; int bi = 0;
        #pragma unroll
        for (int e = 0; e < 4; e++) {
            float g = ex[e] * inv;
            gate_out[4 * t + e] = g;
            if (g > best) { best = g; bi = e; }
        }
        float sig = 1.f / (1.f + expf(-shw[0]));
        g_sw[t] = (1.f - best) * sig;
        int pos = atomicAdd(&g_cnt[bi], 1);
        g_bucket[bi * TOK + pos] = t;
    }
}

// ---------------- aux loss ----------------
__global__ void aux_kernel(const float* __restrict__ gate, float* __restrict__ auxp) {
    __shared__ float4 s[1024];
    int tid = threadIdx.x;
    float4 a = make_float4(0.f, 0.f, 0.f, 0.f);
    for (int t = tid; t < TOK; t += 1024) {
        a.x += gate[4 * t + 0]; a.y += gate[4 * t + 1];
        a.z += gate[4 * t + 2]; a.w += gate[4 * t + 3];
    }
    s[tid] = a;
    __syncthreads();
    for (int off = 512; off > 0; off >>= 1) {
        if (tid < off) {
            s[tid].x += s[tid + off].x; s[tid].y += s[tid + off].y;
            s[tid].z += s[tid + off].z; s[tid].w += s[tid + off].w;
        }
        __syncthreads();
    }
    if (tid == 0) {
        const float invT = 1.f / (float)TOK;
        float gm[4] = { s[0].x * invT, s[0].y * invT, s[0].z * invT, s[0].w * invT };
        float aux = 0.f;
        #pragma unroll
        for (int e = 0; e < NEXP; e++) aux += ((float)g_cnt[e] * invT) * gm[e];
        *auxp = aux * (float)NEXP * 0.01f;
    }
}

// ---------------- fused fp32 -> fp16 convert ----------------
#define N4_X  (TOK * DDIM / 4)
#define N4_W  (NEXP * DDIM * HDIM / 4)
#define N4_S  (DDIM * HDIM / 4)
#define N4_TOTAL (N4_X + 2 * N4_W + 2 * N4_S)

__global__ void convert_all_kernel(const float* __restrict__ x,
                                   const float* __restrict__ W1,
                                   const float* __restrict__ W2,
                                   const float* __restrict__ sW1,
                                   const float* __restrict__ sW2,
                                   __half* xf, __half* w1, __half* w2,
                                   __half* s1, __half* s2) {
    int i = blockIdx.x * blockDim.x + threadIdx.x;
    if (i >= N4_TOTAL) return;
    const float* src; __half* dst; int j = i;
    if (j < N4_X) { src = x; dst = xf; }
    else if ((j -= N4_X) < N4_W) { src = W1; dst = w1; }
    else if ((j -= N4_W) < N4_W) { src = W2; dst = w2; }
    else if ((j -= N4_W) < N4_S) { src = sW1; dst = s1; }
    else { j -= N4_S; src = sW2; dst = s2; }
    float4 v = ((const float4*)src)[j];
    ((__half2*)dst)[2 * j]     = __halves2half2(__float2half(v.x), __float2half(v.y));
    ((__half2*)dst)[2 * j + 1] = __halves2half2(__float2half(v.z), __float2half(v.w));
}

// ---------------- fp16 mma.sync GEMM, CTA 128x256, warp tile 64x64 ----------------
// 8 warps (2 M x 4 N), K-tile 32, 4-stage cp.async, occ 1.
// z<4: expert (token-bucketed gather); z==4: shared expert.
// STAGE 1: A=xf, B=W1[e]/sW1 -> gelu -> fp16 he/hs
// STAGE 2: A=he/hs, B=W2[e]/sW2 -> atomicAdd into zeroed out (shared scaled by g_sw)
#define A_TILE_B 10240                    // 128 rows * 80B
#define B_TILE_B (32 * 528)               // 32 k-rows * (512B data + 16B pad)
#define B_OFF    A_TILE_B
#define STAGE_B  (A_TILE_B + B_TILE_B)    // 27136
#define NSTAGE   4
#define SMEM_GEMM (NSTAGE * STAGE_B)      // 108544

template<int STAGE>
__global__ __launch_bounds__(256, 1)
void mma_gemm(const __half* __restrict__ Ae_g,
              const __half* __restrict__ As_g,
              const __half* __restrict__ Be_g,
              const __half* __restrict__ Bs_g,
              const float* __restrict__ biase,
              const float* __restrict__ biass,
              __half* __restrict__ he,
              __half* __restrict__ hs,
              float* __restrict__ outp,
              int K, int N)
{
    extern __shared__ __align__(16) char smem[];
    const int z = blockIdx.z;
    const bool sp = (z == NEXP);
    int Mtot = TOK;
    const int* bucket = nullptr;
    const __half* Ag = sp ? As_g : Ae_g;
    const __half* Bg = sp ? Bs_g : Be_g + (size_t)z * (size_t)K * N;
    const float* bias = sp ? biass : biase + (size_t)z * N;
    if (!sp) {
        Mtot = g_cnt[z];
        if ((int)(blockIdx.y * 128) >= Mtot) return;
        bucket = g_bucket + z * TOK;
    }
    const int tid = threadIdx.x;
    const int wid = tid >> 5, lane = tid & 31;
    const int mbase = blockIdx.y * 128, nbase = blockIdx.x * 256;
    const uint32_t sb = smem_u32(smem);

    // ---- A loader: rows rA0 (0..63), rA1 (64..127), 16B chunk ck ----
    const int rA0 = tid >> 2, rA1 = 64 + (tid >> 2);
    const int ck  = tid & 3;
    int tok0, tok1; bool v0, v1;
    if (!sp) {
        v0 = (mbase + rA0) < Mtot; tok0 = v0 ? bucket[mbase + rA0] : 0;
        v1 = (mbase + rA1) < Mtot; tok1 = v1 ? bucket[mbase + rA1] : 0;
    } else {
        v0 = v1 = true; tok0 = mbase + rA0; tok1 = mbase + rA1;
    }
    const __half* aP0 = Ag + (size_t)tok0 * K + ck * 8;
    const __half* aP1 = Ag + (size_t)tok1 * K + ck * 8;
    const uint32_t oA0 = (uint32_t)rA0 * 80 + ck * 16;
    const uint32_t oA1 = (uint32_t)rA1 * 80 + ck * 16;

    // ---- B loader: 32 k-rows x 512B, 4 chunks/thread ----
    const int rB = tid >> 3, cB = tid & 7;
    const __half* bp = Bg + (size_t)rB * N + nbase + cB * 8;
    const uint32_t oB = (uint32_t)rB * 528 + cB * 16;

    #define LOAD_STAGE(stg, koff) do {                                       \
        uint32_t b_ = sb + (uint32_t)(stg) * STAGE_B;                        \
        cp16(b_ + oA0, aP0 + (koff), v0);                                    \
        cp16(b_ + oA1, aP1 + (koff), v1);                                    \
        const __half* bk_ = bp + (size_t)(koff) * N;                         \
        cp16(b_ + B_OFF + oB,       bk_,       true);                        \
        cp16(b_ + B_OFF + oB + 128, bk_ + 64,  true);                        \
        cp16(b_ + B_OFF + oB + 256, bk_ + 128, true);                        \
        cp16(b_ + B_OFF + oB + 384, bk_ + 192, true);                        \
    } while (0)

    const int KT = K / 32;
    LOAD_STAGE(0, 0);  CP_COMMIT();
    LOAD_STAGE(1, 32); CP_COMMIT();
    LOAD_STAGE(2, 64); CP_COMMIT();

    // ---- compute mapping: warp tile 64 (M) x 64 (N) ----
    const int warpM = (wid & 1) * 64;
    const int warpN = (wid >> 1) * 64;
    float acc[4][8][4];
    #pragma unroll
    for (int mi = 0; mi < 4; mi++)
        #pragma unroll
        for (int ni = 0; ni < 8; ni++)
            #pragma unroll
            for (int q = 0; q < 4; q++) acc[mi][ni][q] = 0.f;

    const uint32_t aRowOff = (uint32_t)(warpM + (lane & 15)) * 80 + (lane >> 4) * 16;
    const uint32_t bOffBase = (uint32_t)((lane & 7) + ((lane >> 3) & 1) * 8) * 528
                              + (uint32_t)warpN * 2 + (uint32_t)(lane >> 4) * 16;

    int s_c = 0;
    for (int kt = 0; kt < KT; kt++) {
        CP_WAIT2();
        __syncthreads();
        if (kt + 3 < KT) {
            int s_l = s_c + 3; if (s_l >= NSTAGE) s_l -= NSTAGE;
            LOAD_STAGE(s_l, (kt + 3) * 32);
        }
        CP_COMMIT();

        uint32_t base = sb + (uint32_t)s_c * STAGE_B;
        #pragma unroll
        for (int ks = 0; ks < 2; ks++) {
            uint32_t bF[8][2];
            #pragma unroll
            for (int p = 0; p < 4; p++) {
                uint32_t r0, r1, r2, r3;
                ldsm4t(r0, r1, r2, r3,
                       base + B_OFF + bOffBase + (uint32_t)ks * (16 * 528) + (uint32_t)p * 32);
                bF[2 * p][0] = r0; bF[2 * p][1] = r1;
                bF[2 * p + 1][0] = r2; bF[2 * p + 1][1] = r3;
            }
            uint32_t aF[4][4];
            #pragma unroll
            for (int mi = 0; mi < 4; mi++) {
                uint32_t ad = base + aRowOff + (uint32_t)mi * (16 * 80) + ks * 32;
                ldsm4(aF[mi][0], aF[mi][1], aF[mi][2], aF[mi][3], ad);
            }
            #pragma unroll
            for (int mi = 0; mi < 4; mi++)
                #pragma unroll
                for (int ni = 0; ni < 8; ni++)
                    mma16816(acc[mi][ni], aF[mi], bF[ni]);
        }
        s_c = (s_c + 1 == NSTAGE) ? 0 : s_c + 1;
    }

    // ---- epilogue ----
    float bb[8][2];
    #pragma unroll
    for (int ni = 0; ni < 8; ni++) {
        int n = nbase + warpN + ni * 8 + (lane & 3) * 2;
        bb[ni][0] = bias[n]; bb[ni][1] = bias[n + 1];
    }
    __half* hdst = sp ? hs : he;

    #pragma unroll
    for (int mi = 0; mi < 4; mi++) {
        #pragma unroll
        for (int h = 0; h < 2; h++) {
            int pos = mbase + warpM + mi * 16 + (lane >> 2) + h * 8;
            int et; bool ev;
            if (!sp) { ev = pos < Mtot; et = ev ? bucket[pos] : 0; }
            else { ev = true; et = pos; }
            if (!ev) continue;
            float swv = (STAGE == 2 && sp) ? g_sw[et] : 1.f;
            #pragma unroll
            for (int ni = 0; ni < 8; ni++) {
                int n = nbase + warpN + ni * 8 + (lane & 3) * 2;
                float u0 = acc[mi][ni][2 * h]     + bb[ni][0];
                float u1 = acc[mi][ni][2 * h + 1] + bb[ni][1];
                if (STAGE == 1) {
                    u0 = 0.5f * u0 * (1.f + erff(u0 * 0.70710678118f));
                    u1 = 0.5f * u1 * (1.f + erff(u1 * 0.70710678118f));
                    *(__half2*)(hdst + (size_t)et * HDIM + n) =
                        __halves2half2(__float2half(u0), __float2half(u1));
                } else {
                    float* dst = outp + (size_t)et * DDIM + n;
                    atomicAdd(dst,     swv * u0);
                    atomicAdd(dst + 1, swv * u1);
                }
            }
        }
    }
    #undef LOAD_STAGE
}

// ---------------- launch ----------------
extern "C" void kernel_launch(void* const* d_in, const int* in_sizes, int n_in,
                              void* d_out, int out_size) {
    const float* x   = (const float*)d_in[0];
    const float* gW  = (const float*)d_in[1];
    const float* gb  = (const float*)d_in[2];
    const float* W1  = (const float*)d_in[3];
    const float* b1  = (const float*)d_in[4];
    const float* W2  = (const float*)d_in[5];
    const float* b2  = (const float*)d_in[6];
    const float* sW1 = (const float*)d_in[7];
    const float* sb1 = (const float*)d_in[8];
    const float* sW2 = (const float*)d_in[9];
    const float* sb2 = (const float*)d_in[10];
    const float* shw = (const float*)d_in[11];

    float* out  = (float*)d_out;
    float* auxp = out + (size_t)TOK * DDIM;
    float* gate = auxp + 1;

    cudaFuncSetAttribute(mma_gemm<1>, cudaFuncAttributeMaxDynamicSharedMemorySize, SMEM_GEMM);
    cudaFuncSetAttribute(mma_gemm<2>, cudaFuncAttributeMaxDynamicSharedMemorySize, SMEM_GEMM);

    __half *xf, *w1, *w2, *s1, *s2, *he, *hs;
    cudaGetSymbolAddress((void**)&xf, g_xf);
    cudaGetSymbolAddress((void**)&w1, g_w1); cudaGetSymbolAddress((void**)&w2, g_w2);
    cudaGetSymbolAddress((void**)&s1, g_s1); cudaGetSymbolAddress((void**)&s2, g_s2);
    cudaGetSymbolAddress((void**)&he, g_he); cudaGetSymbolAddress((void**)&hs, g_hs);

    zero_kernel<<<1, 32>>>();
    router_kernel<<<TOK / 8, 256>>>(x, gW, gb, shw, gate);
    aux_kernel<<<1, 1024>>>(gate, auxp);
    convert_all_kernel<<<(N4_TOTAL + 255) / 256, 256>>>(
        x, W1, W2, sW1, sW2, xf, w1, w2, s1, s2);
    cudaMemsetAsync(out, 0, (size_t)TOK * DDIM * sizeof(float));

    // stage 1: expert (z 0..3) + shared (z 4) -> he / hs
    mma_gemm<1><<<dim3(HDIM / 256, TOK / 128, NEXP + 1), 256, SMEM_GEMM>>>(
        xf, xf, w1, s1, b1, sb1, he, hs, nullptr, DDIM, HDIM);
    // stage 2: expert + shared -> atomicAdd into out
    mma_gemm<2><<<dim3(DDIM / 256, TOK / 128, NEXP + 1), 256, SMEM_GEMM>>>(
        he, hs, w2, s2, b2, sb2, nullptr, nullptr, out, HDIM, DDIM);
}

// round 7
// speedup vs baseline: 1.1309x; 1.1309x over previous
#include <cuda_runtime.h>
#include <cuda_fp16.h>
#include <math.h>
#include <stdint.h>

#define TOK  8192
#define DDIM 512
#define HDIM 2048
#define NEXP 4

// ---------------- device scratch ----------------
__device__ int   g_cnt[NEXP];
__device__ int   g_bucket[NEXP * TOK];
__device__ float g_sw[TOK];

__device__ __half g_xf[(size_t)TOK * DDIM];
__device__ __half g_he[(size_t)TOK * HDIM];           // expert-path hidden
__device__ __half g_hs[(size_t)TOK * HDIM];           // shared-path hidden
__device__ __half g_w1[(size_t)NEXP * DDIM * HDIM];   // [E][D][H]
__device__ __half g_w2[(size_t)NEXP * HDIM * DDIM];   // [E][H][D]
__device__ __half g_s1[(size_t)DDIM * HDIM];          // [D][H]
__device__ __half g_s2[(size_t)HDIM * DDIM];          // [H][D]

// ---------------- helpers ----------------
__device__ __forceinline__ uint32_t smem_u32(const void* p) {
    uint32_t a;
    asm("{ .reg .u64 t; cvta.to.shared.u64 t, %1; cvt.u32.u64 %0, t; }" : "=r"(a) : "l"(p));
    return a;
}
__device__ __forceinline__ void cp16(uint32_t dst, const void* src, bool valid) {
    int sz = valid ? 16 : 0;
    asm volatile("cp.async.cg.shared.global [%0], [%1], 16, %2;\n" :: "r"(dst), "l"(src), "r"(sz));
}
#define CP_COMMIT() asm volatile("cp.async.commit_group;\n" ::: "memory")
#define CP_WAIT3()  asm volatile("cp.async.wait_group 3;\n" ::: "memory")

__device__ __forceinline__ void ldsm4(uint32_t& r0, uint32_t& r1, uint32_t& r2, uint32_t& r3,
                                      uint32_t a) {
    asm volatile("ldmatrix.sync.aligned.m8n8.x4.shared.b16 {%0,%1,%2,%3}, [%4];"
        : "=r"(r0), "=r"(r1), "=r"(r2), "=r"(r3) : "r"(a));
}
__device__ __forceinline__ void ldsm4t(uint32_t& r0, uint32_t& r1, uint32_t& r2, uint32_t& r3,
                                       uint32_t a) {
    asm volatile("ldmatrix.sync.aligned.m8n8.x4.trans.shared.b16 {%0,%1,%2,%3}, [%4];"
        : "=r"(r0), "=r"(r1), "=r"(r2), "=r"(r3) : "r"(a));
}
__device__ __forceinline__ void mma16816(float* c, const uint32_t* a, const uint32_t* b) {
    asm volatile("mma.sync.aligned.m16n8k16.row.col.f32.f16.f16.f32 "
        "{%0,%1,%2,%3}, {%4,%5,%6,%7}, {%8,%9}, {%0,%1,%2,%3};"
        : "+f"(c[0]), "+f"(c[1]), "+f"(c[2]), "+f"(c[3])
        : "r"(a[0]), "r"(a[1]), "r"(a[2]), "r"(a[3]), "r"(b[0]), "r"(b[1]));
}

// ---------------- zero counters ----------------
__global__ void zero_kernel() {
    if (threadIdx.x < NEXP) g_cnt[threadIdx.x] = 0;
}

// ---------------- router ----------------
__global__ void router_kernel(const float* __restrict__ x,
                              const float* __restrict__ gW,
                              const float* __restrict__ gb,
                              const float* __restrict__ shw,
                              float* __restrict__ gate_out) {
    int t = (blockIdx.x * blockDim.x + threadIdx.x) >> 5;
    int lane = threadIdx.x & 31;
    if (t >= TOK) return;
    const float* xr = x + (size_t)t * DDIM;
    float a0 = 0.f, a1 = 0.f, a2 = 0.f, a3 = 0.f;
    for (int j = lane; j < DDIM; j += 32) {
        float v = xr[j];
        float4 w = *(const float4*)(gW + 4 * j);
        a0 = fmaf(v, w.x, a0); a1 = fmaf(v, w.y, a1);
        a2 = fmaf(v, w.z, a2); a3 = fmaf(v, w.w, a3);
    }
    #pragma unroll
    for (int off = 16; off > 0; off >>= 1) {
        a0 += __shfl_xor_sync(0xffffffffu, a0, off);
        a1 += __shfl_xor_sync(0xffffffffu, a1, off);
        a2 += __shfl_xor_sync(0xffffffffu, a2, off);
        a3 += __shfl_xor_sync(0xffffffffu, a3, off);
    }
    if (lane == 0) {
        float l[4] = {a0 + gb[0], a1 + gb[1], a2 + gb[2], a3 + gb[3]};
        float m = fmaxf(fmaxf(l[0], l[1]), fmaxf(l[2], l[3]));
        float ex[4], s = 0.f;
        #pragma unroll
        for (int e = 0; e < 4; e++) { ex[e] = expf(l[e] - m); s += ex[e]; }
        float inv = 1.f / s;
        float best = -1.f; int bi = 0;
        #pragma unroll
        for (int e = 0; e < 4; e++) {
            float g = ex[e] * inv;
            gate_out[4 * t + e] = g;
            if (g > best) { best = g; bi = e; }
        }
        float sig = 1.f / (1.f + expf(-shw[0]));
        g_sw[t] = (1.f - best) * sig;
        int pos = atomicAdd(&g_cnt[bi], 1);
        g_bucket[bi * TOK + pos] = t;
    }
}

// ---------------- aux loss ----------------
__global__ void aux_kernel(const float* __restrict__ gate, float* __restrict__ auxp) {
    __shared__ float4 s[1024];
    int tid = threadIdx.x;
    float4 a = make_float4(0.f, 0.f, 0.f, 0.f);
    for (int t = tid; t < TOK; t += 1024) {
        a.x += gate[4 * t + 0]; a.y += gate[4 * t + 1];
        a.z += gate[4 * t + 2]; a.w += gate[4 * t + 3];
    }
    s[tid] = a;
    __syncthreads();
    for (int off = 512; off > 0; off >>= 1) {
        if (tid < off) {
            s[tid].x += s[tid + off].x; s[tid].y += s[tid + off].y;
            s[tid].z += s[tid + off].z; s[tid].w += s[tid + off].w;
        }
        __syncthreads();
    }
    if (tid == 0) {
        const float invT = 1.f / (float)TOK;
        float gm[4] = { s[0].x * invT, s[0].y * invT, s[0].z * invT, s[0].w * invT };
        float aux = 0.f;
        #pragma unroll
        for (int e = 0; e < NEXP; e++) aux += ((float)g_cnt[e] * invT) * gm[e];
        *auxp = aux * (float)NEXP * 0.01f;
    }
}

// ---------------- fused fp32 -> fp16 convert ----------------
#define N4_X  (TOK * DDIM / 4)
#define N4_W  (NEXP * DDIM * HDIM / 4)
#define N4_S  (DDIM * HDIM / 4)
#define N4_TOTAL (N4_X + 2 * N4_W + 2 * N4_S)

__global__ void convert_all_kernel(const float* __restrict__ x,
                                   const float* __restrict__ W1,
                                   const float* __restrict__ W2,
                                   const float* __restrict__ sW1,
                                   const float* __restrict__ sW2,
                                   __half* xf, __half* w1, __half* w2,
                                   __half* s1, __half* s2) {
    int i = blockIdx.x * blockDim.x + threadIdx.x;
    if (i >= N4_TOTAL) return;
    const float* src; __half* dst; int j = i;
    if (j < N4_X) { src = x; dst = xf; }
    else if ((j -= N4_X) < N4_W) { src = W1; dst = w1; }
    else if ((j -= N4_W) < N4_W) { src = W2; dst = w2; }
    else if ((j -= N4_W) < N4_S) { src = sW1; dst = s1; }
    else { j -= N4_S; src = sW2; dst = s2; }
    float4 v = ((const float4*)src)[j];
    ((__half2*)dst)[2 * j]     = __halves2half2(__float2half(v.x), __float2half(v.y));
    ((__half2*)dst)[2 * j + 1] = __halves2half2(__float2half(v.z), __float2half(v.w));
}

// ---------------- fp16 mma.sync GEMM, CTA 128x128, warp tile 64x32, 5-stage ----------------
// 8 warps (2 M x 4 N), K-tile 32, 5-stage cp.async, occ 2.
// STAGE 1: A=xf (gathered for z<4), B=W1[e]/sW1 -> gelu -> fp16 he/hs
// STAGE 2: A=he/hs, B=W2[e]/sW2 -> atomicAdd into zeroed out (shared scaled by g_sw)
#define A_TILE_B 10240               // 128 rows * 80B
#define B_TILE_B 8704                // 32 rows * 272B
#define B_OFF    A_TILE_B
#define STAGE_B  (A_TILE_B + B_TILE_B)   // 18944
#define NSTAGE   5
#define SMEM_GEMM (NSTAGE * STAGE_B)     // 94720

template<int STAGE>
__global__ __launch_bounds__(256, 2)
void mma_gemm(const __half* __restrict__ Ae_g,
              const __half* __restrict__ As_g,
              const __half* __restrict__ Be_g,
              const __half* __restrict__ Bs_g,
              const float* __restrict__ biase,
              const float* __restrict__ biass,
              __half* __restrict__ he,
              __half* __restrict__ hs,
              float* __restrict__ outp,
              int K, int N)
{
    extern __shared__ __align__(16) char smem[];
    const int z = blockIdx.z;
    const bool sp = (z == NEXP);
    int Mtot = TOK;
    const int* bucket = nullptr;
    const __half* Ag = sp ? As_g : Ae_g;
    const __half* Bg = sp ? Bs_g : Be_g + (size_t)z * (size_t)K * N;
    const float* bias = sp ? biass : biase + (size_t)z * N;
    if (!sp) {
        Mtot = g_cnt[z];
        if ((int)(blockIdx.y * 128) >= Mtot) return;
        bucket = g_bucket + z * TOK;
    }
    const int tid = threadIdx.x;
    const int wid = tid >> 5, lane = tid & 31;
    const int mbase = blockIdx.y * 128, nbase = blockIdx.x * 128;
    const uint32_t sb = smem_u32(smem);

    // ---- A loader: rows rA0 (0..63), rA1 (64..127), 16B chunk ck ----
    const int rA0 = tid >> 2, rA1 = 64 + (tid >> 2);
    const int ck  = tid & 3;
    int tok0, tok1; bool v0, v1;
    if (!sp) {
        v0 = (mbase + rA0) < Mtot; tok0 = v0 ? bucket[mbase + rA0] : 0;
        v1 = (mbase + rA1) < Mtot; tok1 = v1 ? bucket[mbase + rA1] : 0;
    } else {
        v0 = v1 = true; tok0 = mbase + rA0; tok1 = mbase + rA1;
    }
    const __half* aP0 = Ag + (size_t)tok0 * K + ck * 8;
    const __half* aP1 = Ag + (size_t)tok1 * K + ck * 8;
    const uint32_t oA0 = (uint32_t)rA0 * 80 + ck * 16;
    const uint32_t oA1 = (uint32_t)rA1 * 80 + ck * 16;

    // ---- B loader: 32 k-rows x 256B ----
    const int rB = tid >> 3, cB = tid & 7;
    const __half* bp = Bg + (size_t)rB * N + nbase + cB * 8;
    const uint32_t oB = (uint32_t)rB * 272 + cB * 16;

    #define LOAD_STAGE(stg, koff) do {                                       \
        uint32_t b_ = sb + (uint32_t)(stg) * STAGE_B;                        \
        cp16(b_ + oA0, aP0 + (koff), v0);                                    \
        cp16(b_ + oA1, aP1 + (koff), v1);                                    \
        cp16(b_ + B_OFF + oB,       bp + (size_t)(koff) * N, true);          \
        cp16(b_ + B_OFF + oB + 128, bp + (size_t)(koff) * N + 64, true);     \
    } while (0)

    const int KT = K / 32;
    LOAD_STAGE(0, 0);  CP_COMMIT();
    LOAD_STAGE(1, 32); CP_COMMIT();
    LOAD_STAGE(2, 64); CP_COMMIT();
    LOAD_STAGE(3, 96); CP_COMMIT();

    // ---- compute mapping: warp tile 64 (M) x 32 (N) ----
    const int warpM = (wid & 1) * 64;
    const int warpN = (wid >> 1) * 32;
    float acc[4][4][4];
    #pragma unroll
    for (int mi = 0; mi < 4; mi++)
        #pragma unroll
        for (int ni = 0; ni < 4; ni++)
            #pragma unroll
            for (int q = 0; q < 4; q++) acc[mi][ni][q] = 0.f;

    const uint32_t aRowOff = (uint32_t)(warpM + (lane & 15)) * 80 + (lane >> 4) * 16;
    const uint32_t bOffBase = (uint32_t)((lane & 7) + ((lane >> 3) & 1) * 8) * 272
                              + (uint32_t)warpN * 2 + (uint32_t)(lane >> 4) * 16;

    int s_c = 0;
    for (int kt = 0; kt < KT; kt++) {
        CP_WAIT3();
        __syncthreads();
        if (kt + 4 < KT) {
            int s_l = s_c + 4; if (s_l >= NSTAGE) s_l -= NSTAGE;
            LOAD_STAGE(s_l, (kt + 4) * 32);
        }
        CP_COMMIT();

        uint32_t base = sb + (uint32_t)s_c * STAGE_B;
        #pragma unroll
        for (int ks = 0; ks < 2; ks++) {
            uint32_t bF[4][2];
            #pragma unroll
            for (int p = 0; p < 2; p++) {
                uint32_t r0, r1, r2, r3;
                ldsm4t(r0, r1, r2, r3,
                       base + B_OFF + bOffBase + (uint32_t)ks * (16 * 272) + (uint32_t)p * 32);
                bF[2 * p][0] = r0; bF[2 * p][1] = r1;
                bF[2 * p + 1][0] = r2; bF[2 * p + 1][1] = r3;
            }
            uint32_t aF[4][4];
            #pragma unroll
            for (int mi = 0; mi < 4; mi++) {
                uint32_t ad = base + aRowOff + (uint32_t)mi * (16 * 80) + ks * 32;
                ldsm4(aF[mi][0], aF[mi][1], aF[mi][2], aF[mi][3], ad);
            }
            #pragma unroll
            for (int mi = 0; mi < 4; mi++)
                #pragma unroll
                for (int ni = 0; ni < 4; ni++)
                    mma16816(acc[mi][ni], aF[mi], bF[ni]);
        }
        s_c = (s_c + 1 == NSTAGE) ? 0 : s_c + 1;
    }

    // ---- epilogue ----
    float bb[4][2];
    #pragma unroll
    for (int ni = 0; ni < 4; ni++) {
        int n = nbase + warpN + ni * 8 + (lane & 3) * 2;
        bb[ni][0] = bias[n]; bb[ni][1] = bias[n + 1];
    }
    __half* hdst = sp ? hs : he;

    #pragma unroll
    for (int mi = 0; mi < 4; mi++) {
        #pragma unroll
        for (int h = 0; h < 2; h++) {
            int pos = mbase + warpM + mi * 16 + (lane >> 2) + h * 8;
            int et; bool ev;
            if (!sp) { ev = pos < Mtot; et = ev ? bucket[pos] : 0; }
            else { ev = true; et = pos; }
            if (!ev) continue;
            float swv = (STAGE == 2 && sp) ? g_sw[et] : 1.f;
            #pragma unroll
            for (int ni = 0; ni < 4; ni++) {
                int n = nbase + warpN + ni * 8 + (lane & 3) * 2;
                float u0 = acc[mi][ni][2 * h]     + bb[ni][0];
                float u1 = acc[mi][ni][2 * h + 1] + bb[ni][1];
                if (STAGE == 1) {
                    u0 = 0.5f * u0 * (1.f + erff(u0 * 0.70710678118f));
                    u1 = 0.5f * u1 * (1.f + erff(u1 * 0.70710678118f));
                    *(__half2*)(hdst + (size_t)et * HDIM + n) =
                        __halves2half2(__float2half(u0), __float2half(u1));
                } else {
                    float* dst = outp + (size_t)et * DDIM + n;
                    atomicAdd(dst,     swv * u0);
                    atomicAdd(dst + 1, swv * u1);
                }
            }
        }
    }
    #undef LOAD_STAGE
}

// ---------------- launch ----------------
extern "C" void kernel_launch(void* const* d_in, const int* in_sizes, int n_in,
                              void* d_out, int out_size) {
    const float* x   = (const float*)d_in[0];
    const float* gW  = (const float*)d_in[1];
    const float* gb  = (const float*)d_in[2];
    const float* W1  = (const float*)d_in[3];
    const float* b1  = (const float*)d_in[4];
    const float* W2  = (const float*)d_in[5];
    const float* b2  = (const float*)d_in[6];
    const float* sW1 = (const float*)d_in[7];
    const float* sb1 = (const float*)d_in[8];
    const float* sW2 = (const float*)d_in[9];
    const float* sb2 = (const float*)d_in[10];
    const float* shw = (const float*)d_in[11];

    float* out  = (float*)d_out;
    float* auxp = out + (size_t)TOK * DDIM;
    float* gate = auxp + 1;

    cudaFuncSetAttribute(mma_gemm<1>, cudaFuncAttributeMaxDynamicSharedMemorySize, SMEM_GEMM);
    cudaFuncSetAttribute(mma_gemm<2>, cudaFuncAttributeMaxDynamicSharedMemorySize, SMEM_GEMM);

    __half *xf, *w1, *w2, *s1, *s2, *he, *hs;
    cudaGetSymbolAddress((void**)&xf, g_xf);
    cudaGetSymbolAddress((void**)&w1, g_w1); cudaGetSymbolAddress((void**)&w2, g_w2);
    cudaGetSymbolAddress((void**)&s1, g_s1); cudaGetSymbolAddress((void**)&s2, g_s2);
    cudaGetSymbolAddress((void**)&he, g_he); cudaGetSymbolAddress((void**)&hs, g_hs);

    // side stream + events (host-side handles; created once, no device memory)
    static cudaStream_t s_side = nullptr;
    static cudaEvent_t  ev_fork = nullptr, ev_join = nullptr;
    if (!s_side) {
        cudaStreamCreateWithFlags(&s_side, cudaStreamNonBlocking);
        cudaEventCreateWithFlags(&ev_fork, cudaEventDisableTiming);
        cudaEventCreateWithFlags(&ev_join, cudaEventDisableTiming);
    }

    // fork: conversions + out-zeroing run on side stream, overlapped with router/aux
    cudaEventRecord(ev_fork, 0);
    cudaStreamWaitEvent(s_side, ev_fork, 0);
    convert_all_kernel<<<(N4_TOTAL + 255) / 256, 256, 0, s_side>>>(
        x, W1, W2, sW1, sW2, xf, w1, w2, s1, s2);
    cudaMemsetAsync(out, 0, (size_t)TOK * DDIM * sizeof(float), s_side);
    cudaEventRecord(ev_join, s_side);

    // main stream: routing chain
    zero_kernel<<<1, 32>>>();
    router_kernel<<<TOK / 8, 256>>>(x, gW, gb, shw, gate);
    aux_kernel<<<1, 1024>>>(gate, auxp);

    // join before GEMMs
    cudaStreamWaitEvent(0, ev_join, 0);

    // stage 1: expert (z 0..3) + shared (z 4) -> he / hs
    mma_gemm<1><<<dim3(HDIM / 128, TOK / 128, NEXP + 1), 256, SMEM_GEMM>>>(
        xf, xf, w1, s1, b1, sb1, he, hs, nullptr, DDIM, HDIM);
    // stage 2: expert + shared -> atomicAdd into out
    mma_gemm<2><<<dim3(DDIM / 128, TOK / 128, NEXP + 1), 256, SMEM_GEMM>>>(
        he, hs, w2, s2, b2, sb2, nullptr, nullptr, out, HDIM, DDIM);
}

// round 8
// speedup vs baseline: 1.1566x; 1.0227x over previous
#include <cuda_runtime.h>
#include <cuda_fp16.h>
#include <math.h>
#include <stdint.h>

#define TOK  8192
#define DDIM 512
#define HDIM 2048
#define NEXP 4

// ---------------- device scratch ----------------
__device__ int   g_cnt[NEXP];
__device__ int   g_bucket[NEXP * TOK];
__device__ float g_sw[TOK];

__device__ __half g_xf[(size_t)TOK * DDIM];
__device__ __half g_he[(size_t)TOK * HDIM];           // expert-path hidden
__device__ __half g_hs[(size_t)TOK * HDIM];           // shared-path hidden
__device__ __half g_w1[(size_t)NEXP * DDIM * HDIM];   // [E][D][H]
__device__ __half g_w2[(size_t)NEXP * HDIM * DDIM];   // [E][H][D]
__device__ __half g_s1[(size_t)DDIM * HDIM];          // [D][H]
__device__ __half g_s2[(size_t)HDIM * DDIM];          // [H][D]

// ---------------- helpers ----------------
__device__ __forceinline__ uint32_t smem_u32(const void* p) {
    uint32_t a;
    asm("{ .reg .u64 t; cvta.to.shared.u64 t, %1; cvt.u32.u64 %0, t; }" : "=r"(a) : "l"(p));
    return a;
}
__device__ __forceinline__ void cp16(uint32_t dst, const void* src, bool valid) {
    int sz = valid ? 16 : 0;
    asm volatile("cp.async.cg.shared.global [%0], [%1], 16, %2;\n" :: "r"(dst), "l"(src), "r"(sz));
}
#define CP_COMMIT() asm volatile("cp.async.commit_group;\n" ::: "memory")
#define CP_WAIT2()  asm volatile("cp.async.wait_group 2;\n" ::: "memory")

__device__ __forceinline__ void ldsm4(uint32_t& r0, uint32_t& r1, uint32_t& r2, uint32_t& r3,
                                      uint32_t a) {
    asm volatile("ldmatrix.sync.aligned.m8n8.x4.shared.b16 {%0,%1,%2,%3}, [%4];"
        : "=r"(r0), "=r"(r1), "=r"(r2), "=r"(r3) : "r"(a));
}
__device__ __forceinline__ void ldsm4t(uint32_t& r0, uint32_t& r1, uint32_t& r2, uint32_t& r3,
                                       uint32_t a) {
    asm volatile("ldmatrix.sync.aligned.m8n8.x4.trans.shared.b16 {%0,%1,%2,%3}, [%4];"
        : "=r"(r0), "=r"(r1), "=r"(r2), "=r"(r3) : "r"(a));
}
__device__ __forceinline__ void mma16816(float* c, const uint32_t* a, const uint32_t* b) {
    asm volatile("mma.sync.aligned.m16n8k16.row.col.f32.f16.f16.f32 "
        "{%0,%1,%2,%3}, {%4,%5,%6,%7}, {%8,%9}, {%0,%1,%2,%3};"
        : "+f"(c[0]), "+f"(c[1]), "+f"(c[2]), "+f"(c[3])
        : "r"(a[0]), "r"(a[1]), "r"(a[2]), "r"(a[3]), "r"(b[0]), "r"(b[1]));
}

// ---------------- zero counters ----------------
__global__ void zero_kernel() {
    if (threadIdx.x < NEXP) g_cnt[threadIdx.x] = 0;
}

// ---------------- router ----------------
__global__ void router_kernel(const float* __restrict__ x,
                              const float* __restrict__ gW,
                              const float* __restrict__ gb,
                              const float* __restrict__ shw,
                              float* __restrict__ gate_out) {
    int t = (blockIdx.x * blockDim.x + threadIdx.x) >> 5;
    int lane = threadIdx.x & 31;
    if (t >= TOK) return;
    const float* xr = x + (size_t)t * DDIM;
    float a0 = 0.f, a1 = 0.f, a2 = 0.f, a3 = 0.f;
    for (int j = lane; j < DDIM; j += 32) {
        float v = xr[j];
        float4 w = *(const float4*)(gW + 4 * j);
        a0 = fmaf(v, w.x, a0); a1 = fmaf(v, w.y, a1);
        a2 = fmaf(v, w.z, a2); a3 = fmaf(v, w.w, a3);
    }
    #pragma unroll
    for (int off = 16; off > 0; off >>= 1) {
        a0 += __shfl_xor_sync(0xffffffffu, a0, off);
        a1 += __shfl_xor_sync(0xffffffffu, a1, off);
        a2 += __shfl_xor_sync(0xffffffffu, a2, off);
        a3 += __shfl_xor_sync(0xffffffffu, a3, off);
    }
    if (lane == 0) {
        float l[4] = {a0 + gb[0], a1 + gb[1], a2 + gb[2], a3 + gb[3]};
        float m = fmaxf(fmaxf(l[0], l[1]), fmaxf(l[2], l[3]));
        float ex[4], s = 0.f;
        #pragma unroll
        for (int e = 0; e < 4; e++) { ex[e] = expf(l[e] - m); s += ex[e]; }
        float inv = 1.f / s;
        float best = -1.f; int bi = 0;
        #pragma unroll
        for (int e = 0; e < 4; e++) {
            float g = ex[e] * inv;
            gate_out[4 * t + e] = g;
            if (g > best) { best = g; bi = e; }
        }
        float sig = 1.f / (1.f + expf(-shw[0]));
        g_sw[t] = (1.f - best) * sig;
        int pos = atomicAdd(&g_cnt[bi], 1);
        g_bucket[bi * TOK + pos] = t;
    }
}

// ---------------- aux loss ----------------
__global__ void aux_kernel(const float* __restrict__ gate, float* __restrict__ auxp) {
    __shared__ float4 s[1024];
    int tid = threadIdx.x;
    float4 a = make_float4(0.f, 0.f, 0.f, 0.f);
    for (int t = tid; t < TOK; t += 1024) {
        a.x += gate[4 * t + 0]; a.y += gate[4 * t + 1];
        a.z += gate[4 * t + 2]; a.w += gate[4 * t + 3];
    }
    s[tid] = a;
    __syncthreads();
    for (int off = 512; off > 0; off >>= 1) {
        if (tid < off) {
            s[tid].x += s[tid + off].x; s[tid].y += s[tid + off].y;
            s[tid].z += s[tid + off].z; s[tid].w += s[tid + off].w;
        }
        __syncthreads();
    }
    if (tid == 0) {
        const float invT = 1.f / (float)TOK;
        float gm[4] = { s[0].x * invT, s[0].y * invT, s[0].z * invT, s[0].w * invT };
        float aux = 0.f;
        #pragma unroll
        for (int e = 0; e < NEXP; e++) aux += ((float)g_cnt[e] * invT) * gm[e];
        *auxp = aux * (float)NEXP * 0.01f;
    }
}

// ---------------- fused fp32 -> fp16 convert ----------------
#define N4_X  (TOK * DDIM / 4)
#define N4_W  (NEXP * DDIM * HDIM / 4)
#define N4_S  (DDIM * HDIM / 4)
#define N4_TOTAL (N4_X + 2 * N4_W + 2 * N4_S)

__global__ void convert_all_kernel(const float* __restrict__ x,
                                   const float* __restrict__ W1,
                                   const float* __restrict__ W2,
                                   const float* __restrict__ sW1,
                                   const float* __restrict__ sW2,
                                   __half* xf, __half* w1, __half* w2,
                                   __half* s1, __half* s2) {
    int i = blockIdx.x * blockDim.x + threadIdx.x;
    if (i >= N4_TOTAL) return;
    const float* src; __half* dst; int j = i;
    if (j < N4_X) { src = x; dst = xf; }
    else if ((j -= N4_X) < N4_W) { src = W1; dst = w1; }
    else if ((j -= N4_W) < N4_W) { src = W2; dst = w2; }
    else if ((j -= N4_W) < N4_S) { src = sW1; dst = s1; }
    else { j -= N4_S; src = sW2; dst = s2; }
    float4 v = ((const float4*)src)[j];
    ((__half2*)dst)[2 * j]     = __halves2half2(__float2half(v.x), __float2half(v.y));
    ((__half2*)dst)[2 * j + 1] = __halves2half2(__float2half(v.z), __float2half(v.w));
}

// ---------------- fp16 mma.sync GEMM, CTA 128x128, warp tile 64x32, 4-stage ----------------
// (exactly the R5 measured-best configuration)
#define A_TILE_B 10240               // 128 rows * 80B
#define B_TILE_B 8704                // 32 rows * 272B
#define B_OFF    A_TILE_B
#define STAGE_B  (A_TILE_B + B_TILE_B)   // 18944
#define NSTAGE   4
#define SMEM_GEMM (NSTAGE * STAGE_B)     // 75776

template<int STAGE>
__global__ __launch_bounds__(256, 2)
void mma_gemm(const __half* __restrict__ Ae_g,
              const __half* __restrict__ As_g,
              const __half* __restrict__ Be_g,
              const __half* __restrict__ Bs_g,
              const float* __restrict__ biase,
              const float* __restrict__ biass,
              __half* __restrict__ he,
              __half* __restrict__ hs,
              float* __restrict__ outp,
              int K, int N)
{
    extern __shared__ __align__(16) char smem[];
    const int z = blockIdx.z;
    const bool sp = (z == NEXP);
    int Mtot = TOK;
    const int* bucket = nullptr;
    const __half* Ag = sp ? As_g : Ae_g;
    const __half* Bg = sp ? Bs_g : Be_g + (size_t)z * (size_t)K * N;
    const float* bias = sp ? biass : biase + (size_t)z * N;
    if (!sp) {
        Mtot = g_cnt[z];
        if ((int)(blockIdx.y * 128) >= Mtot) return;
        bucket = g_bucket + z * TOK;
    }
    const int tid = threadIdx.x;
    const int wid = tid >> 5, lane = tid & 31;
    const int mbase = blockIdx.y * 128, nbase = blockIdx.x * 128;
    const uint32_t sb = smem_u32(smem);

    // ---- A loader ----
    const int rA0 = tid >> 2, rA1 = 64 + (tid >> 2);
    const int ck  = tid & 3;
    int tok0, tok1; bool v0, v1;
    if (!sp) {
        v0 = (mbase + rA0) < Mtot; tok0 = v0 ? bucket[mbase + rA0] : 0;
        v1 = (mbase + rA1) < Mtot; tok1 = v1 ? bucket[mbase + rA1] : 0;
    } else {
        v0 = v1 = true; tok0 = mbase + rA0; tok1 = mbase + rA1;
    }
    const __half* aP0 = Ag + (size_t)tok0 * K + ck * 8;
    const __half* aP1 = Ag + (size_t)tok1 * K + ck * 8;
    const uint32_t oA0 = (uint32_t)rA0 * 80 + ck * 16;
    const uint32_t oA1 = (uint32_t)rA1 * 80 + ck * 16;

    // ---- B loader ----
    const int rB = tid >> 3, cB = tid & 7;
    const __half* bp = Bg + (size_t)rB * N + nbase + cB * 8;
    const uint32_t oB = (uint32_t)rB * 272 + cB * 16;

    #define LOAD_STAGE(stg, koff) do {                                       \
        uint32_t b_ = sb + (uint32_t)(stg) * STAGE_B;                        \
        cp16(b_ + oA0, aP0 + (koff), v0);                                    \
        cp16(b_ + oA1, aP1 + (koff), v1);                                    \
        cp16(b_ + B_OFF + oB,       bp + (size_t)(koff) * N, true);          \
        cp16(b_ + B_OFF + oB + 128, bp + (size_t)(koff) * N + 64, true);     \
    } while (0)

    const int KT = K / 32;
    LOAD_STAGE(0, 0);  CP_COMMIT();
    LOAD_STAGE(1, 32); CP_COMMIT();
    LOAD_STAGE(2, 64); CP_COMMIT();

    // ---- compute mapping: warp tile 64 (M) x 32 (N) ----
    const int warpM = (wid & 1) * 64;
    const int warpN = (wid >> 1) * 32;
    float acc[4][4][4];
    #pragma unroll
    for (int mi = 0; mi < 4; mi++)
        #pragma unroll
        for (int ni = 0; ni < 4; ni++)
            #pragma unroll
            for (int q = 0; q < 4; q++) acc[mi][ni][q] = 0.f;

    const uint32_t aRowOff = (uint32_t)(warpM + (lane & 15)) * 80 + (lane >> 4) * 16;
    const uint32_t bOffBase = (uint32_t)((lane & 7) + ((lane >> 3) & 1) * 8) * 272
                              + (uint32_t)warpN * 2 + (uint32_t)(lane >> 4) * 16;

    int s_c = 0;
    for (int kt = 0; kt < KT; kt++) {
        CP_WAIT2();
        __syncthreads();
        if (kt + 3 < KT) {
            int s_l = s_c + 3; if (s_l >= NSTAGE) s_l -= NSTAGE;
            LOAD_STAGE(s_l, (kt + 3) * 32);
        }
        CP_COMMIT();

        uint32_t base = sb + (uint32_t)s_c * STAGE_B;
        #pragma unroll
        for (int ks = 0; ks < 2; ks++) {
            uint32_t bF[4][2];
            #pragma unroll
            for (int p = 0; p < 2; p++) {
                uint32_t r0, r1, r2, r3;
                ldsm4t(r0, r1, r2, r3,
                       base + B_OFF + bOffBase + (uint32_t)ks * (16 * 272) + (uint32_t)p * 32);
                bF[2 * p][0] = r0; bF[2 * p][1] = r1;
                bF[2 * p + 1][0] = r2; bF[2 * p + 1][1] = r3;
            }
            uint32_t aF[4][4];
            #pragma unroll
            for (int mi = 0; mi < 4; mi++) {
                uint32_t ad = base + aRowOff + (uint32_t)mi * (16 * 80) + ks * 32;
                ldsm4(aF[mi][0], aF[mi][1], aF[mi][2], aF[mi][3], ad);
            }
            #pragma unroll
            for (int mi = 0; mi < 4; mi++)
                #pragma unroll
                for (int ni = 0; ni < 4; ni++)
                    mma16816(acc[mi][ni], aF[mi], bF[ni]);
        }
        s_c = (s_c + 1 == NSTAGE) ? 0 : s_c + 1;
    }

    // ---- epilogue ----
    float bb[4][2];
    #pragma unroll
    for (int ni = 0; ni < 4; ni++) {
        int n = nbase + warpN + ni * 8 + (lane & 3) * 2;
        bb[ni][0] = bias[n]; bb[ni][1] = bias[n + 1];
    }
    __half* hdst = sp ? hs : he;

    #pragma unroll
    for (int mi = 0; mi < 4; mi++) {
        #pragma unroll
        for (int h = 0; h < 2; h++) {
            int pos = mbase + warpM + mi * 16 + (lane >> 2) + h * 8;
            int et; bool ev;
            if (!sp) { ev = pos < Mtot; et = ev ? bucket[pos] : 0; }
            else { ev = true; et = pos; }
            if (!ev) continue;
            float swv = (STAGE == 2 && sp) ? g_sw[et] : 1.f;
            #pragma unroll
            for (int ni = 0; ni < 4; ni++) {
                int n = nbase + warpN + ni * 8 + (lane & 3) * 2;
                float u0 = acc[mi][ni][2 * h]     + bb[ni][0];
                float u1 = acc[mi][ni][2 * h + 1] + bb[ni][1];
                if (STAGE == 1) {
                    u0 = 0.5f * u0 * (1.f + erff(u0 * 0.70710678118f));
                    u1 = 0.5f * u1 * (1.f + erff(u1 * 0.70710678118f));
                    *(__half2*)(hdst + (size_t)et * HDIM + n) =
                        __halves2half2(__float2half(u0), __float2half(u1));
                } else {
                    float* dst = outp + (size_t)et * DDIM + n;
                    atomicAdd(dst,     swv * u0);
                    atomicAdd(dst + 1, swv * u1);
                }
            }
        }
    }
    #undef LOAD_STAGE
}

// ---------------- launch ----------------
extern "C" void kernel_launch(void* const* d_in, const int* in_sizes, int n_in,
                              void* d_out, int out_size) {
    const float* x   = (const float*)d_in[0];
    const float* gW  = (const float*)d_in[1];
    const float* gb  = (const float*)d_in[2];
    const float* W1  = (const float*)d_in[3];
    const float* b1  = (const float*)d_in[4];
    const float* W2  = (const float*)d_in[5];
    const float* b2  = (const float*)d_in[6];
    const float* sW1 = (const float*)d_in[7];
    const float* sb1 = (const float*)d_in[8];
    const float* sW2 = (const float*)d_in[9];
    const float* sb2 = (const float*)d_in[10];
    const float* shw = (const float*)d_in[11];

    float* out  = (float*)d_out;
    float* auxp = out + (size_t)TOK * DDIM;
    float* gate = auxp + 1;

    cudaFuncSetAttribute(mma_gemm<1>, cudaFuncAttributeMaxDynamicSharedMemorySize, SMEM_GEMM);
    cudaFuncSetAttribute(mma_gemm<2>, cudaFuncAttributeMaxDynamicSharedMemorySize, SMEM_GEMM);

    __half *xf, *w1, *w2, *s1, *s2, *he, *hs;
    cudaGetSymbolAddress((void**)&xf, g_xf);
    cudaGetSymbolAddress((void**)&w1, g_w1); cudaGetSymbolAddress((void**)&w2, g_w2);
    cudaGetSymbolAddress((void**)&s1, g_s1); cudaGetSymbolAddress((void**)&s2, g_s2);
    cudaGetSymbolAddress((void**)&he, g_he); cudaGetSymbolAddress((void**)&hs, g_hs);

    static cudaStream_t s_side = nullptr;
    static cudaEvent_t  ev_fork = nullptr, ev_conv = nullptr, ev_router = nullptr, ev_aux = nullptr;
    if (!s_side) {
        cudaStreamCreateWithFlags(&s_side, cudaStreamNonBlocking);
        cudaEventCreateWithFlags(&ev_fork,   cudaEventDisableTiming);
        cudaEventCreateWithFlags(&ev_conv,   cudaEventDisableTiming);
        cudaEventCreateWithFlags(&ev_router, cudaEventDisableTiming);
        cudaEventCreateWithFlags(&ev_aux,    cudaEventDisableTiming);
    }

    // fork side stream
    cudaEventRecord(ev_fork, 0);
    cudaStreamWaitEvent(s_side, ev_fork, 0);

    // side: conversions + out zeroing (independent of router)
    convert_all_kernel<<<(N4_TOTAL + 255) / 256, 256, 0, s_side>>>(
        x, W1, W2, sW1, sW2, xf, w1, w2, s1, s2);
    cudaMemsetAsync(out, 0, (size_t)TOK * DDIM * sizeof(float), s_side);
    cudaEventRecord(ev_conv, s_side);

    // main: routing chain
    zero_kernel<<<1, 32>>>();
    router_kernel<<<TOK / 8, 256>>>(x, gW, gb, shw, gate);
    cudaEventRecord(ev_router, 0);

    // side: aux runs concurrently with GEMM1 (needs router results only)
    cudaStreamWaitEvent(s_side, ev_router, 0);
    aux_kernel<<<1, 1024, 0, s_side>>>(gate, auxp);
    cudaEventRecord(ev_aux, s_side);

    // main: GEMMs gated only on conversions
    cudaStreamWaitEvent(0, ev_conv, 0);
    mma_gemm<1><<<dim3(HDIM / 128, TOK / 128, NEXP + 1), 256, SMEM_GEMM>>>(
        xf, xf, w1, s1, b1, sb1, he, hs, nullptr, DDIM, HDIM);
    mma_gemm<2><<<dim3(DDIM / 128, TOK / 128, NEXP + 1), 256, SMEM_GEMM>>>(
        he, hs, w2, s2, b2, sb2, nullptr, nullptr, out, HDIM, DDIM);

    // join side stream for capture completeness (no critical-path cost)
    cudaStreamWaitEvent(0, ev_aux, 0);
}